// round 2
// baseline (speedup 1.0000x reference)
#include <cuda_runtime.h>
#include <math.h>

typedef unsigned long long u64;

// Problem constants (fixed shapes from the reference)
#define Bdim 4
#define Hdim 8
#define Tdim 512
#define Ddim 512
#define DhD  64
#define NL   64     // number of lag candidates
#define KTOP 18     // top-k lags = 2*ceil(log2(512)) = 18
#define NSLOT 19    // 1 (lag 0 / instantaneous) + KTOP
#define BH   (Bdim*Hdim)

// lags for T=512, LMAX=64: step=7 -> 1,8,...,442 then last forced to 511
__device__ __forceinline__ int lag_of(int l) { return (l == NL-1) ? (Tdim-1) : (1 + 7*l); }

// ---------------- packed f32x2 helpers (FFMA2) ------------------------------
__device__ __forceinline__ u64 pk2(float lo, float hi) {
    u64 r; asm("mov.b64 %0,{%1,%2};" : "=l"(r) : "f"(lo), "f"(hi)); return r;
}
__device__ __forceinline__ u64 dup2(float v) { return pk2(v, v); }
__device__ __forceinline__ void fma2(u64 &d, u64 a, u64 b) {
    asm("fma.rn.f32x2 %0,%1,%2,%0;" : "+l"(d) : "l"(a), "l"(b));
}
__device__ __forceinline__ void unpk(u64 v, float &lo, float &hi) {
    asm("mov.b64 {%0,%1},%2;" : "=f"(lo), "=f"(hi) : "l"(v));
}

// ---------------- scratch (static device memory; no runtime allocation) ----
__device__ float g_Q[BH*Tdim*DhD];                 // 4 MB, normalized in place
__device__ float g_K[BH*Tdim*DhD];                 // 4 MB, normalized in place
__device__ float g_V[BH*Tdim*DhD];                 // 4 MB
__device__ float g_cov[(size_t)BH*(NL+1)*DhD*DhD]; // 34 MB (slot NL = lag 0)
__device__ float g_score[BH*NL];
__device__ int   g_shift[BH*NSLOT];
__device__ float g_wslot[BH*NSLOT];
__device__ int   g_covsel[BH*NSLOT];
__device__ float g_attw[(size_t)BH*NSLOT*DhD*DhD]; // 10 MB
__device__ float g_outh[Bdim*Tdim*Ddim];           // 4 MB, [B,T,D] layout

// ---------------- GEMM: C[M=2048, N=512] = A[2048,512] @ W[512,512] + bias --
// 64x64 block tile, BK=16, 128 threads, 4(m)x8(n) per-thread micro-tile in
// packed f32x2. a_sel: 0 -> A_ext, 1 -> g_outh.
// c_sel: 0 -> C_ext plain [M,512]; 1/2/3 -> g_Q/K/V head-major.
__global__ void gemm64(const float* __restrict__ A_ext, int a_sel,
                       const float* __restrict__ W, const float* __restrict__ bias,
                       float* __restrict__ C_ext, int c_sel)
{
    __shared__ float As[16][68];  // As[k][m]
    __shared__ float Bs[16][68];  // Bs[k][n]
    const float* A = (a_sel == 0) ? A_ext : g_outh;
    const int tid = threadIdx.x;            // 128 threads
    const int tx = tid & 7, ty = tid >> 3;  // tx 0..7 (n), ty 0..15 (m)
    const int m0 = blockIdx.x * 64, n0 = blockIdx.y * 64;
    u64 acc[4][4];
    #pragma unroll
    for (int i = 0; i < 4; i++)
        #pragma unroll
        for (int j = 0; j < 4; j++) acc[i][j] = 0ull;

    for (int k0 = 0; k0 < Ddim; k0 += 16) {
        #pragma unroll
        for (int p = tid; p < 256; p += 128) {
            // A tile: 64 m x 16 k (transpose on store)
            int arow = p >> 2, ak = (p & 3) << 2;
            float4 v = *(const float4*)(A + (size_t)(m0 + arow)*Ddim + k0 + ak);
            As[ak+0][arow] = v.x; As[ak+1][arow] = v.y;
            As[ak+2][arow] = v.z; As[ak+3][arow] = v.w;
            // B tile: 16 k x 64 n (direct)
            int brow = p >> 4, bn = (p & 15) << 2;
            *(float4*)&Bs[brow][bn] = *(const float4*)(W + (size_t)(k0 + brow)*Ddim + n0 + bn);
        }
        __syncthreads();
        #pragma unroll
        for (int kk = 0; kk < 16; kk++) {
            float4 av = *(const float4*)&As[kk][ty*4];
            u64 a2[4] = {dup2(av.x), dup2(av.y), dup2(av.z), dup2(av.w)};
            float4 b0 = *(const float4*)&Bs[kk][tx*8];
            float4 b1 = *(const float4*)&Bs[kk][tx*8 + 4];
            u64 b2[4] = {pk2(b0.x,b0.y), pk2(b0.z,b0.w), pk2(b1.x,b1.y), pk2(b1.z,b1.w)};
            #pragma unroll
            for (int i = 0; i < 4; i++)
                #pragma unroll
                for (int j = 0; j < 4; j++) fma2(acc[i][j], a2[i], b2[j]);
        }
        __syncthreads();
    }
    #pragma unroll
    for (int i = 0; i < 4; i++) {
        int m = m0 + ty*4 + i;
        #pragma unroll
        for (int j = 0; j < 4; j++) {
            int n = n0 + tx*8 + 2*j;
            float lo, hi; unpk(acc[i][j], lo, hi);
            lo += bias[n]; hi += bias[n+1];
            if (c_sel == 0) {
                *(float2*)(C_ext + (size_t)m*Ddim + n) = make_float2(lo, hi);
            } else {
                float* C = (c_sel == 1) ? g_Q : (c_sel == 2) ? g_K : g_V;
                int b = m >> 9, t = m & (Tdim-1), h = n >> 6, c = n & (DhD-1);
                *(float2*)(C + (((size_t)(b*Hdim + h))*Tdim + t)*DhD + c) = make_float2(lo, hi);
            }
        }
    }
}

// ---------------- L2-normalize Q and K over the time axis --------------------
// grid (BH, 2), 256 threads: 64 d-columns x 4 t-groups, coalesced.
__global__ void normalize_kernel()
{
    __shared__ float part[256];
    __shared__ float sinv[DhD];
    int bh = blockIdx.x;
    float* base = (blockIdx.y ? g_K : g_Q) + (size_t)bh*Tdim*DhD;
    int d = threadIdx.x & 63, g = threadIdx.x >> 6;
    float s = 0.f;
    for (int t = g*128; t < (g+1)*128; t++) {
        float v = base[t*DhD + d]; s = fmaf(v, v, s);
    }
    part[threadIdx.x] = s;
    __syncthreads();
    if (threadIdx.x < 64) {
        float tot = part[d] + part[d+64] + part[d+128] + part[d+192];
        sinv[d] = 1.0f / sqrtf(fmaxf(tot, 1e-8f));
    }
    __syncthreads();
    float inv = sinv[d];
    for (int t = g*128; t < (g+1)*128; t++) base[t*DhD + d] *= inv;
}

// ---------------- cov[bh][l][d][c] = sum_t Khat[(t-lag)%T][d] * Qhat[t][c] ---
// l in [0,64]; l==64 is lag 0 (the instantaneous cov0). Fuses the lag score.
__global__ void cov_kernel(const float* __restrict__ lam_ptr)
{
    __shared__ float Ks[32][68];   // [t][d]
    __shared__ float Qs[32][68];   // [t][c]
    __shared__ float red1[128];
    __shared__ float red2[128];
    const int l = blockIdx.x, bh = blockIdx.y;
    const int lag = (l == NL) ? 0 : lag_of(l);
    const float* Kb = g_K + (size_t)bh*Tdim*DhD;
    const float* Qb = g_Q + (size_t)bh*Tdim*DhD;
    const int tid = threadIdx.x, tx = tid & 7, ty = tid >> 3;
    u64 acc[4][4];
    #pragma unroll
    for (int i = 0; i < 4; i++)
        #pragma unroll
        for (int j = 0; j < 4; j++) acc[i][j] = 0ull;

    for (int t0 = 0; t0 < Tdim; t0 += 32) {
        #pragma unroll
        for (int p = tid; p < 512; p += 128) {
            int row = p >> 4, c4 = (p & 15) << 2;
            *(float4*)&Qs[row][c4] = *(const float4*)(Qb + (t0 + row)*DhD + c4);
            int src = (t0 + row - lag + Tdim) & (Tdim - 1);
            *(float4*)&Ks[row][c4] = *(const float4*)(Kb + src*DhD + c4);
        }
        __syncthreads();
        #pragma unroll 16
        for (int tt = 0; tt < 32; tt++) {
            float4 av = *(const float4*)&Ks[tt][ty*4];
            u64 a2[4] = {dup2(av.x), dup2(av.y), dup2(av.z), dup2(av.w)};
            float4 b0 = *(const float4*)&Qs[tt][tx*8];
            float4 b1 = *(const float4*)&Qs[tt][tx*8 + 4];
            u64 b2[4] = {pk2(b0.x,b0.y), pk2(b0.z,b0.w), pk2(b1.x,b1.y), pk2(b1.z,b1.w)};
            #pragma unroll
            for (int i = 0; i < 4; i++)
                #pragma unroll
                for (int j = 0; j < 4; j++) fma2(acc[i][j], a2[i], b2[j]);
        }
        __syncthreads();
    }
    float* covp = g_cov + ((size_t)bh*(NL+1) + l) * (DhD*DhD);
    float tot = 0.f, dia = 0.f;
    #pragma unroll
    for (int i = 0; i < 4; i++) {
        int d = ty*4 + i;
        #pragma unroll
        for (int j = 0; j < 4; j++) {
            int c = tx*8 + 2*j;
            float lo, hi; unpk(acc[i][j], lo, hi);
            *(float2*)(covp + d*DhD + c) = make_float2(lo, hi);
            tot += fabsf(lo) + fabsf(hi);
            if (d == c)     dia += fabsf(lo);
            if (d == c + 1) dia += fabsf(hi);
        }
    }
    if (l < NL) {
        red1[tid] = tot; red2[tid] = dia;
        __syncthreads();
        for (int s = 64; s > 0; s >>= 1) {
            if (tid < s) { red1[tid] += red1[tid+s]; red2[tid] += red2[tid+s]; }
            __syncthreads();
        }
        if (tid == 0) {
            float lam = fminf(fmaxf(*lam_ptr, 0.f), 1.f);
            g_score[bh*NL + l] = lam*red2[0] + (1.f - lam)*(red1[0] - red2[0]);
        }
    }
}

// ---------------- top-18 lag selection + slot weights ------------------------
__global__ void topk_kernel(const float* __restrict__ lt_lag,
                            const float* __restrict__ beta_ptr)
{
    int bh = threadIdx.x;
    if (bh >= BH) return;
    float sc[NL];
    for (int l = 0; l < NL; l++) sc[l] = g_score[bh*NL + l];
    float selVal[KTOP]; int selIdx[KTOP];
    for (int k = 0; k < KTOP; k++) {
        float best = -3.4e38f; int bi = 0;
        for (int l = 0; l < NL; l++) if (sc[l] > best) { best = sc[l]; bi = l; }
        selVal[k] = best; selIdx[k] = bi; sc[bi] = -3.4e38f;
    }
    float tl = fmaxf(expf(*lt_lag), 1e-4f);
    float mx = selVal[0];
    float e[KTOP], esum = 0.f;
    for (int k = 0; k < KTOP; k++) { e[k] = expf((selVal[k] - mx)/tl); esum += e[k]; }
    float beta = fminf(fmaxf(*beta_ptr, 0.f), 1.f);
    g_shift[bh*NSLOT]  = 0;
    g_wslot[bh*NSLOT]  = 1.f - beta;
    g_covsel[bh*NSLOT] = NL;
    for (int k = 0; k < KTOP; k++) {
        g_shift[bh*NSLOT + 1 + k]  = lag_of(selIdx[k]);
        g_wslot[bh*NSLOT + 1 + k]  = beta * e[k] / esum;
        g_covsel[bh*NSLOT + 1 + k] = selIdx[k];
    }
}

// ---------------- attw[s] = weight_s * softmax_c(cov_sel / tau) --------------
__global__ void att_kernel(const float* __restrict__ log_tau_ptr)
{
    const int s = blockIdx.x, bh = blockIdx.y;
    const int l = g_covsel[bh*NSLOT + s];
    const float w = g_wslot[bh*NSLOT + s];
    const float invtau = 1.0f / fmaxf(expf(*log_tau_ptr), 1e-4f);
    const float* covp = g_cov + ((size_t)bh*(NL+1) + l)*(DhD*DhD);
    float* outp = g_attw + ((size_t)bh*NSLOT + s)*(DhD*DhD);
    int warp = threadIdx.x >> 5, lane = threadIdx.x & 31;
    for (int d = warp; d < DhD; d += 8) {
        float v0 = covp[d*DhD + lane]      * invtau;
        float v1 = covp[d*DhD + lane + 32] * invtau;
        float m = fmaxf(v0, v1);
        #pragma unroll
        for (int o = 16; o > 0; o >>= 1) m = fmaxf(m, __shfl_xor_sync(0xffffffffu, m, o));
        float e0 = expf(v0 - m), e1 = expf(v1 - m);
        float ss = e0 + e1;
        #pragma unroll
        for (int o = 16; o > 0; o >>= 1) ss += __shfl_xor_sync(0xffffffffu, ss, o);
        float f = w / ss;
        outp[d*DhD + lane]      = e0 * f;
        outp[d*DhD + lane + 32] = e1 * f;
    }
}

// ---------------- out_h[t,c] = sum_s sum_d V[(t-shift_s)%T, d] * attw_s[d,c] --
__global__ void contrib_kernel()
{
    __shared__ float VsT[64][68];   // [d][t] (transposed on store)
    __shared__ float Att[64][68];   // [d][c]
    const int bh = blockIdx.y, t0 = blockIdx.x * 64;
    const int bb = bh >> 3, hh = bh & 7;
    const float* Vb = g_V + (size_t)bh*Tdim*DhD;
    const int tid = threadIdx.x, tx = tid & 7, ty = tid >> 3;
    u64 acc[4][4];
    #pragma unroll
    for (int i = 0; i < 4; i++)
        #pragma unroll
        for (int j = 0; j < 4; j++) acc[i][j] = 0ull;

    for (int s = 0; s < NSLOT; s++) {
        const int shift = g_shift[bh*NSLOT + s];
        const float* ap = g_attw + ((size_t)bh*NSLOT + s)*(DhD*DhD);
        #pragma unroll
        for (int p = tid; p < 1024; p += 128) {
            int row = p >> 4, c4 = (p & 15) << 2;
            *(float4*)&Att[row][c4] = *(const float4*)(ap + row*DhD + c4);
            int src = (t0 + row - shift + Tdim) & (Tdim - 1);
            float4 v = *(const float4*)(Vb + src*DhD + c4);
            VsT[c4+0][row] = v.x; VsT[c4+1][row] = v.y;
            VsT[c4+2][row] = v.z; VsT[c4+3][row] = v.w;
        }
        __syncthreads();
        #pragma unroll 16
        for (int dd = 0; dd < 64; dd++) {
            float4 av = *(const float4*)&VsT[dd][ty*4];
            u64 a2[4] = {dup2(av.x), dup2(av.y), dup2(av.z), dup2(av.w)};
            float4 b0 = *(const float4*)&Att[dd][tx*8];
            float4 b1 = *(const float4*)&Att[dd][tx*8 + 4];
            u64 b2[4] = {pk2(b0.x,b0.y), pk2(b0.z,b0.w), pk2(b1.x,b1.y), pk2(b1.z,b1.w)};
            #pragma unroll
            for (int i = 0; i < 4; i++)
                #pragma unroll
                for (int j = 0; j < 4; j++) fma2(acc[i][j], a2[i], b2[j]);
        }
        __syncthreads();
    }
    #pragma unroll
    for (int i = 0; i < 4; i++) {
        int t = t0 + ty*4 + i;
        #pragma unroll
        for (int j = 0; j < 4; j++) {
            int c = tx*8 + 2*j;
            float lo, hi; unpk(acc[i][j], lo, hi);
            *(float2*)(g_outh + ((size_t)(bb*Tdim + t))*Ddim + hh*DhD + c) = make_float2(lo, hi);
        }
    }
}

// ---------------- launch ------------------------------------------------------
extern "C" void kernel_launch(void* const* d_in, const int* in_sizes, int n_in,
                              void* d_out, int out_size)
{
    const float* x           = (const float*)d_in[0];
    const float* Wq          = (const float*)d_in[1];
    const float* bq          = (const float*)d_in[2];
    const float* Wk          = (const float*)d_in[3];
    const float* bk          = (const float*)d_in[4];
    const float* Wv          = (const float*)d_in[5];
    const float* bv          = (const float*)d_in[6];
    const float* Wo          = (const float*)d_in[7];
    const float* bo          = (const float*)d_in[8];
    const float* log_tau     = (const float*)d_in[9];
    const float* lambda_auto = (const float*)d_in[10];
    const float* beta_lag    = (const float*)d_in[11];
    const float* log_tau_lag = (const float*)d_in[12];
    float* out = (float*)d_out;

    dim3 ggrid(Bdim*Tdim/64, Ddim/64);   // 32 x 8

    gemm64<<<ggrid, 128>>>(x, 0, Wq, bq, nullptr, 1);
    gemm64<<<ggrid, 128>>>(x, 0, Wk, bk, nullptr, 2);
    gemm64<<<ggrid, 128>>>(x, 0, Wv, bv, nullptr, 3);
    normalize_kernel<<<dim3(BH, 2), 256>>>();
    cov_kernel<<<dim3(NL+1, BH), 128>>>(lambda_auto);
    topk_kernel<<<1, 32>>>(log_tau_lag, beta_lag);
    att_kernel<<<dim3(NSLOT, BH), 256>>>(log_tau);
    contrib_kernel<<<dim3(Tdim/64, BH), 128>>>();
    gemm64<<<ggrid, 128>>>(nullptr, 1, Wo, bo, out, 0);
}

// round 3
// speedup vs baseline: 1.2832x; 1.2832x over previous
#include <cuda_runtime.h>
#include <math.h>

// Problem constants (fixed shapes from the reference)
#define Bdim 4
#define Hdim 8
#define Tdim 512
#define Ddim 512
#define DhD  64
#define NL   64     // number of lag candidates
#define KTOP 18     // top-k lags = 2*ceil(log2(512)) = 18
#define NSLOT 19    // 1 (lag 0 / instantaneous) + KTOP
#define BH   (Bdim*Hdim)

// lags for T=512, LMAX=64: step=7 -> 1,8,...,442 then last forced to 511
__device__ __forceinline__ int lag_of(int l) { return (l == NL-1) ? (Tdim-1) : (1 + 7*l); }

// ---------------- scratch (static device memory; no runtime allocation) ----
__device__ float g_Q[BH*Tdim*DhD];                 // 4 MB, normalized in place
__device__ float g_K[BH*Tdim*DhD];                 // 4 MB, normalized in place
__device__ float g_V[BH*Tdim*DhD];                 // 4 MB
__device__ float g_cov[(size_t)BH*(NL+1)*DhD*DhD]; // 34 MB (slot NL = lag 0)
__device__ float g_score[BH*NL];
__device__ int   g_shift[BH*NSLOT];
__device__ float g_wslot[BH*NSLOT];
__device__ int   g_covsel[BH*NSLOT];
__device__ float g_attw[(size_t)BH*NSLOT*DhD*DhD]; // 10 MB
__device__ float g_outh[Bdim*Tdim*Ddim];           // 4 MB, [B,T,D] layout

// ---------------- QKV GEMM: one launch, z selects Q/K/V ---------------------
// C[M=2048, N=512] = x[2048,512] @ W[512,512] + bias, scattered head-major.
// 64x64 block tile, BK=32, 256 threads, 4x4 per-thread micro-tile.
__global__ void gemm_qkv(const float* __restrict__ x,
                         const float* __restrict__ Wq, const float* __restrict__ bq,
                         const float* __restrict__ Wk, const float* __restrict__ bk,
                         const float* __restrict__ Wv, const float* __restrict__ bv)
{
    __shared__ float As[32][68];  // As[k][m]
    __shared__ float Bs[32][68];  // Bs[k][n]
    const int z = blockIdx.z;
    const float* W    = (z == 0) ? Wq : (z == 1) ? Wk : Wv;
    const float* bias = (z == 0) ? bq : (z == 1) ? bk : bv;
    float* C          = (z == 0) ? g_Q : (z == 1) ? g_K : g_V;
    const int tid = threadIdx.x;
    const int tx = tid & 15, ty = tid >> 4;
    const int m0 = blockIdx.x * 64, n0 = blockIdx.y * 64;
    float acc[4][4] = {};
    for (int k0 = 0; k0 < Ddim; k0 += 32) {
        #pragma unroll
        for (int p = tid; p < 512; p += 256) {
            // A tile: 64 m x 32 k (transpose on store)
            int arow = p >> 3, ak = (p & 7) << 2;
            float4 v = *(const float4*)(x + (size_t)(m0 + arow)*Ddim + k0 + ak);
            As[ak+0][arow] = v.x; As[ak+1][arow] = v.y;
            As[ak+2][arow] = v.z; As[ak+3][arow] = v.w;
            // B tile: 32 k x 64 n (direct)
            int brow = p >> 4, bn = (p & 15) << 2;
            *(float4*)&Bs[brow][bn] = *(const float4*)(W + (size_t)(k0 + brow)*Ddim + n0 + bn);
        }
        __syncthreads();
        #pragma unroll 16
        for (int kk = 0; kk < 32; kk++) {
            float a[4], b[4];
            #pragma unroll
            for (int i = 0; i < 4; i++) a[i] = As[kk][ty + 16*i];
            #pragma unroll
            for (int j = 0; j < 4; j++) b[j] = Bs[kk][tx + 16*j];
            #pragma unroll
            for (int i = 0; i < 4; i++)
                #pragma unroll
                for (int j = 0; j < 4; j++)
                    acc[i][j] = fmaf(a[i], b[j], acc[i][j]);
        }
        __syncthreads();
    }
    #pragma unroll
    for (int i = 0; i < 4; i++) {
        int m = m0 + ty + 16*i;
        int b = m >> 9, t = m & (Tdim-1);
        #pragma unroll
        for (int j = 0; j < 4; j++) {
            int n = n0 + tx + 16*j;
            int h = n >> 6, c = n & (DhD-1);
            C[(((size_t)(b*Hdim + h))*Tdim + t)*DhD + c] = acc[i][j] + bias[n];
        }
    }
}

// ---------------- output GEMM: out[M,512] = g_outh @ Wo + bo -----------------
__global__ void gemm_out(const float* __restrict__ Wo, const float* __restrict__ bo,
                         float* __restrict__ out)
{
    __shared__ float As[32][68];
    __shared__ float Bs[32][68];
    const int tid = threadIdx.x;
    const int tx = tid & 15, ty = tid >> 4;
    const int m0 = blockIdx.x * 64, n0 = blockIdx.y * 64;
    float acc[4][4] = {};
    for (int k0 = 0; k0 < Ddim; k0 += 32) {
        #pragma unroll
        for (int p = tid; p < 512; p += 256) {
            int arow = p >> 3, ak = (p & 7) << 2;
            float4 v = *(const float4*)(g_outh + (size_t)(m0 + arow)*Ddim + k0 + ak);
            As[ak+0][arow] = v.x; As[ak+1][arow] = v.y;
            As[ak+2][arow] = v.z; As[ak+3][arow] = v.w;
            int brow = p >> 4, bn = (p & 15) << 2;
            *(float4*)&Bs[brow][bn] = *(const float4*)(Wo + (size_t)(k0 + brow)*Ddim + n0 + bn);
        }
        __syncthreads();
        #pragma unroll 16
        for (int kk = 0; kk < 32; kk++) {
            float a[4], b[4];
            #pragma unroll
            for (int i = 0; i < 4; i++) a[i] = As[kk][ty + 16*i];
            #pragma unroll
            for (int j = 0; j < 4; j++) b[j] = Bs[kk][tx + 16*j];
            #pragma unroll
            for (int i = 0; i < 4; i++)
                #pragma unroll
                for (int j = 0; j < 4; j++)
                    acc[i][j] = fmaf(a[i], b[j], acc[i][j]);
        }
        __syncthreads();
    }
    #pragma unroll
    for (int i = 0; i < 4; i++) {
        int m = m0 + ty + 16*i;
        #pragma unroll
        for (int j = 0; j < 4; j++) {
            int n = n0 + tx + 16*j;
            out[(size_t)m*Ddim + n] = acc[i][j] + bo[n];
        }
    }
}

// ---------------- L2-normalize Q and K over the time axis --------------------
// grid (BH, 2), 512 threads: 64 d-columns x 8 t-groups, coalesced.
__global__ void normalize_kernel()
{
    __shared__ float part[512];
    __shared__ float sinv[DhD];
    int bh = blockIdx.x;
    float* base = (blockIdx.y ? g_K : g_Q) + (size_t)bh*Tdim*DhD;
    int d = threadIdx.x & 63, g = threadIdx.x >> 6;
    float s = 0.f;
    for (int t = g*64; t < (g+1)*64; t++) {
        float v = base[t*DhD + d]; s = fmaf(v, v, s);
    }
    part[threadIdx.x] = s;
    __syncthreads();
    if (threadIdx.x < 64) {
        float tot = 0.f;
        #pragma unroll
        for (int g2 = 0; g2 < 8; g2++) tot += part[d + g2*64];
        sinv[d] = 1.0f / sqrtf(fmaxf(tot, 1e-8f));
    }
    __syncthreads();
    float inv = sinv[d];
    for (int t = g*64; t < (g+1)*64; t++) base[t*DhD + d] *= inv;
}

// ---------------- cov[bh][l][d][c] = sum_t Khat[(t-lag)%T][d] * Qhat[t][c] ---
// l in [0,64]; l==64 is lag 0 (the instantaneous cov0). Fuses the lag score.
// BK=64 over t: 8 tile iterations, 2 syncs each.
__global__ void cov_kernel(const float* __restrict__ lam_ptr)
{
    __shared__ float Ks[64][68];   // [t][d]
    __shared__ float Qs[64][68];   // [t][c]
    __shared__ float red1[256];
    __shared__ float red2[256];
    const int l = blockIdx.x, bh = blockIdx.y;
    const int lag = (l == NL) ? 0 : lag_of(l);
    const float* Kb = g_K + (size_t)bh*Tdim*DhD;
    const float* Qb = g_Q + (size_t)bh*Tdim*DhD;
    const int tid = threadIdx.x, tx = tid & 15, ty = tid >> 4;
    float acc[4][4] = {};
    for (int t0 = 0; t0 < Tdim; t0 += 64) {
        #pragma unroll
        for (int p = tid; p < 1024; p += 256) {
            int row = p >> 4, c4 = (p & 15) << 2;
            *(float4*)&Qs[row][c4] = *(const float4*)(Qb + (t0 + row)*DhD + c4);
            int src = (t0 + row - lag + Tdim) & (Tdim - 1);
            *(float4*)&Ks[row][c4] = *(const float4*)(Kb + src*DhD + c4);
        }
        __syncthreads();
        #pragma unroll 16
        for (int tt = 0; tt < 64; tt++) {
            float a[4], b[4];
            #pragma unroll
            for (int i = 0; i < 4; i++) a[i] = Ks[tt][ty + 16*i];
            #pragma unroll
            for (int j = 0; j < 4; j++) b[j] = Qs[tt][tx + 16*j];
            #pragma unroll
            for (int i = 0; i < 4; i++)
                #pragma unroll
                for (int j = 0; j < 4; j++)
                    acc[i][j] = fmaf(a[i], b[j], acc[i][j]);
        }
        __syncthreads();
    }
    float* covp = g_cov + ((size_t)bh*(NL+1) + l) * (DhD*DhD);
    float tot = 0.f, dia = 0.f;
    #pragma unroll
    for (int i = 0; i < 4; i++) {
        int d = ty + 16*i;
        #pragma unroll
        for (int j = 0; j < 4; j++) {
            int c = tx + 16*j;
            covp[d*DhD + c] = acc[i][j];
            float av = fabsf(acc[i][j]);
            tot += av;
            if (d == c) dia += av;
        }
    }
    if (l < NL) {
        red1[tid] = tot; red2[tid] = dia;
        __syncthreads();
        for (int s = 128; s > 0; s >>= 1) {
            if (tid < s) { red1[tid] += red1[tid+s]; red2[tid] += red2[tid+s]; }
            __syncthreads();
        }
        if (tid == 0) {
            float lam = fminf(fmaxf(*lam_ptr, 0.f), 1.f);
            g_score[bh*NL + l] = lam*red2[0] + (1.f - lam)*(red1[0] - red2[0]);
        }
    }
}

// ---------------- top-18 lag selection + slot weights ------------------------
__global__ void topk_kernel(const float* __restrict__ lt_lag,
                            const float* __restrict__ beta_ptr)
{
    int bh = threadIdx.x;
    if (bh >= BH) return;
    float sc[NL];
    for (int l = 0; l < NL; l++) sc[l] = g_score[bh*NL + l];
    float selVal[KTOP]; int selIdx[KTOP];
    for (int k = 0; k < KTOP; k++) {
        float best = -3.4e38f; int bi = 0;
        for (int l = 0; l < NL; l++) if (sc[l] > best) { best = sc[l]; bi = l; }
        selVal[k] = best; selIdx[k] = bi; sc[bi] = -3.4e38f;
    }
    float tl = fmaxf(expf(*lt_lag), 1e-4f);
    float mx = selVal[0];
    float e[KTOP], esum = 0.f;
    for (int k = 0; k < KTOP; k++) { e[k] = expf((selVal[k] - mx)/tl); esum += e[k]; }
    float beta = fminf(fmaxf(*beta_ptr, 0.f), 1.f);
    g_shift[bh*NSLOT]  = 0;
    g_wslot[bh*NSLOT]  = 1.f - beta;
    g_covsel[bh*NSLOT] = NL;
    for (int k = 0; k < KTOP; k++) {
        g_shift[bh*NSLOT + 1 + k]  = lag_of(selIdx[k]);
        g_wslot[bh*NSLOT + 1 + k]  = beta * e[k] / esum;
        g_covsel[bh*NSLOT + 1 + k] = selIdx[k];
    }
}

// ---------------- attw[s] = weight_s * softmax_c(cov_sel / tau) --------------
__global__ void att_kernel(const float* __restrict__ log_tau_ptr)
{
    const int s = blockIdx.x, bh = blockIdx.y;
    const int l = g_covsel[bh*NSLOT + s];
    const float w = g_wslot[bh*NSLOT + s];
    const float invtau = 1.0f / fmaxf(expf(*log_tau_ptr), 1e-4f);
    const float* covp = g_cov + ((size_t)bh*(NL+1) + l)*(DhD*DhD);
    float* outp = g_attw + ((size_t)bh*NSLOT + s)*(DhD*DhD);
    int warp = threadIdx.x >> 5, lane = threadIdx.x & 31;
    for (int d = warp; d < DhD; d += 8) {
        float v0 = covp[d*DhD + lane]      * invtau;
        float v1 = covp[d*DhD + lane + 32] * invtau;
        float m = fmaxf(v0, v1);
        #pragma unroll
        for (int o = 16; o > 0; o >>= 1) m = fmaxf(m, __shfl_xor_sync(0xffffffffu, m, o));
        float e0 = expf(v0 - m), e1 = expf(v1 - m);
        float ss = e0 + e1;
        #pragma unroll
        for (int o = 16; o > 0; o >>= 1) ss += __shfl_xor_sync(0xffffffffu, ss, o);
        float f = w / ss;
        outp[d*DhD + lane]      = e0 * f;
        outp[d*DhD + lane + 32] = e1 * f;
    }
}

// ---------------- out_h[t,c] = sum_s sum_d V[(t-shift_s)%T, d] * attw_s[d,c] --
__global__ void contrib_kernel()
{
    __shared__ float Att[64][68];
    __shared__ float Vs[64][68];
    const int bh = blockIdx.y, t0 = blockIdx.x * 64;
    const int bb = bh >> 3, hh = bh & 7;
    const float* Vb = g_V + (size_t)bh*Tdim*DhD;
    const int tid = threadIdx.x, tx = tid & 15, ty = tid >> 4;
    float acc[4][4] = {};
    for (int s = 0; s < NSLOT; s++) {
        const int shift = g_shift[bh*NSLOT + s];
        const float* ap = g_attw + ((size_t)bh*NSLOT + s)*(DhD*DhD);
        #pragma unroll
        for (int p = tid; p < 1024; p += 256) {
            int row = p >> 4, c4 = (p & 15) << 2;
            *(float4*)&Att[row][c4] = *(const float4*)(ap + row*DhD + c4);
            int src = (t0 + row - shift + Tdim) & (Tdim - 1);
            *(float4*)&Vs[row][c4] = *(const float4*)(Vb + src*DhD + c4);
        }
        __syncthreads();
        #pragma unroll 16
        for (int dd = 0; dd < 64; dd++) {
            float a[4], b[4];
            #pragma unroll
            for (int i = 0; i < 4; i++) a[i] = Vs[ty + 16*i][dd];
            #pragma unroll
            for (int j = 0; j < 4; j++) b[j] = Att[dd][tx + 16*j];
            #pragma unroll
            for (int i = 0; i < 4; i++)
                #pragma unroll
                for (int j = 0; j < 4; j++)
                    acc[i][j] = fmaf(a[i], b[j], acc[i][j]);
        }
        __syncthreads();
    }
    #pragma unroll
    for (int i = 0; i < 4; i++) {
        int t = t0 + ty + 16*i;
        #pragma unroll
        for (int j = 0; j < 4; j++) {
            int c = tx + 16*j;
            g_outh[((size_t)(bb*Tdim + t))*Ddim + hh*DhD + c] = acc[i][j];
        }
    }
}

// ---------------- launch ------------------------------------------------------
extern "C" void kernel_launch(void* const* d_in, const int* in_sizes, int n_in,
                              void* d_out, int out_size)
{
    const float* x           = (const float*)d_in[0];
    const float* Wq          = (const float*)d_in[1];
    const float* bq          = (const float*)d_in[2];
    const float* Wk          = (const float*)d_in[3];
    const float* bk          = (const float*)d_in[4];
    const float* Wv          = (const float*)d_in[5];
    const float* bv          = (const float*)d_in[6];
    const float* Wo          = (const float*)d_in[7];
    const float* bo          = (const float*)d_in[8];
    const float* log_tau     = (const float*)d_in[9];
    const float* lambda_auto = (const float*)d_in[10];
    const float* beta_lag    = (const float*)d_in[11];
    const float* log_tau_lag = (const float*)d_in[12];
    float* out = (float*)d_out;

    gemm_qkv<<<dim3(Bdim*Tdim/64, Ddim/64, 3), 256>>>(x, Wq, bq, Wk, bk, Wv, bv);
    normalize_kernel<<<dim3(BH, 2), 512>>>();
    cov_kernel<<<dim3(NL+1, BH), 256>>>(lambda_auto);
    topk_kernel<<<1, 32>>>(log_tau_lag, beta_lag);
    att_kernel<<<dim3(NSLOT, BH), 256>>>(log_tau);
    contrib_kernel<<<dim3(Tdim/64, BH), 256>>>();
    gemm_out<<<dim3(Bdim*Tdim/64, Ddim/64), 256>>>(Wo, bo, out);
}